// round 9
// baseline (speedup 1.0000x reference)
#include <cuda_runtime.h>
#include <math.h>

// Problem dims
#define B_DIM 32
#define F_DIM 1024
#define NG    25
#define NFRM  (B_DIM * F_DIM)

// Scratch for gli (B,F,25) — static __device__ array (allocation-free per harness rules)
__device__ float g_gli[NFRM * NG];

// Segment tables (16 segments across 5 paths)
// paths: [2,5,8,11], [1,4,7,10], [3,6,9,12,15], [14,17,19,21], [13,16,18,20]
__constant__ unsigned char c_ss[16]   = {2,5,8, 1,4,7, 3,6,9,12, 14,17,19, 13,16,18};
__constant__ unsigned char c_se[16]   = {5,8,11, 4,7,10, 6,9,12,15, 17,19,21, 16,18,20};
__constant__ unsigned char c_base[5]  = {0,3,6,10,13};
__constant__ unsigned char c_cnt[5]   = {3,3,4,3,3};

struct V3 { float x, y, z; };
__device__ __forceinline__ V3 vsub(V3 a, V3 b) { return {a.x-b.x, a.y-b.y, a.z-b.z}; }
__device__ __forceinline__ V3 vcrs(V3 a, V3 b) {
    return {a.y*b.z - a.z*b.y, a.z*b.x - a.x*b.z, a.x*b.y - a.y*b.x};
}
__device__ __forceinline__ float vdot(V3 a, V3 b) { return a.x*b.x + a.y*b.y + a.z*b.z; }

// asin( clip( dot(fa,fb)/(|fa||fb|) ) ), with zero-norm -> 0 (matches reference where())
__device__ __forceinline__ float edge_term(float d, float qa, float qb) {
    float p = qa * qb;
    float r = rsqrtf(p);
    r = r * (1.5f - 0.5f * p * r * r);   // one Newton step -> full fp32 precision
    float v = (p > 0.f) ? d * r : 0.f;
    v = fminf(fmaxf(v, -1.f + 1e-7f), 1.f - 1e-7f);
    return asinf(v);
}

__global__ __launch_bounds__(256)
void gli_kernel(const float* __restrict__ m1, const float* __restrict__ m2)
{
    __shared__ float J1[66];          // 22 joints x 3 of motion1 for this frame
    __shared__ float J2[66];
    __shared__ float gall[256];       // per-pair Gauss integrals
    __shared__ unsigned char ss[16], se[16];

    const int  t  = threadIdx.x;
    const long bf = blockIdx.x;       // frame index b*F + f

    if (t < 66)        J1[t]      = m1[bf * 66 + t];
    else if (t < 132)  J2[t - 66] = m2[bf * 66 + (t - 66)];
    if (t < 16) { ss[t] = c_ss[t]; se[t] = c_se[t]; }
    __syncthreads();

    // pair (i: motion1 segment, j: motion2 segment)
    const int i = t >> 4;
    const int j = t & 15;
    const int a1 = 3 * (int)ss[i], b1 = 3 * (int)se[i];
    const int a2 = 3 * (int)ss[j], b2 = 3 * (int)se[j];

    V3 s1 = {J1[a1], J1[a1+1], J1[a1+2]};
    V3 e1 = {J1[b1], J1[b1+1], J1[b1+2]};
    V3 s2 = {J2[a2], J2[a2+1], J2[a2+2]};
    V3 e2 = {J2[b2], J2[b2+1], J2[b2+2]};

    V3 r13 = vsub(s2, s1), r14 = vsub(e2, s1);
    V3 r23 = vsub(s2, e1), r24 = vsub(e2, e1);
    V3 r12 = vsub(e1, s1), r34 = vsub(e2, s2);

    V3 f0 = vcrs(r13, r14);
    V3 f1 = vcrs(r14, r24);
    V3 f2 = vcrs(r24, r23);
    V3 f3 = vcrs(r23, r13);

    float q0 = vdot(f0, f0), q1 = vdot(f1, f1);
    float q2 = vdot(f2, f2), q3 = vdot(f3, f3);

    float g = edge_term(vdot(f0, f1), q0, q1)
            + edge_term(vdot(f1, f2), q1, q2)
            + edge_term(vdot(f2, f3), q2, q3)
            + edge_term(vdot(f3, f0), q3, q0);

    float sgn = vdot(vcrs(r34, r12), r13);
    g = (sgn <= 0.f) ? -g : g;
    gall[t] = g * 0.07957747154594767f;   // 1/(4*pi)
    __syncthreads();

    // Deterministic fixed-order reduction into the 25 path-pair channels.
    if (t < NG) {
        const int a = t / 5;
        const int b = t - 5 * a;
        const int i0 = c_base[a], na = c_cnt[a];
        const int j0 = c_base[b], nb = c_cnt[b];
        float s = 0.f;
        for (int u = 0; u < na; u++)
            for (int v = 0; v < nb; v++)
                s += gall[(i0 + u) * 16 + (j0 + v)];
        g_gli[bf * NG + t] = s;
    }
}

__global__ void vel_kernel(float* __restrict__ out)
{
    const int n = B_DIM * (F_DIM - 1);
    int idx = blockIdx.x * blockDim.x + threadIdx.x;
    if (idx >= n) return;
    int b = idx / (F_DIM - 1);
    int f = idx - b * (F_DIM - 1);
    const float* g0 = g_gli + ((long)b * F_DIM + f) * NG;
    float m = 0.f;
#pragma unroll
    for (int c = 0; c < NG; c++)
        m = fmaxf(m, fabsf(g0[NG + c] - g0[c]));
    out[idx] = m;
}

extern "C" void kernel_launch(void* const* d_in, const int* in_sizes, int n_in,
                              void* d_out, int out_size)
{
    const float* m1 = (const float*)d_in[0];   // motion1 (32,1024,22,3) f32
    const float* m2 = (const float*)d_in[1];   // motion2 (32,1024,22,3) f32
    float* out = (float*)d_out;                // (32,1023) f32

    gli_kernel<<<NFRM, 256>>>(m1, m2);

    const int n = B_DIM * (F_DIM - 1);
    vel_kernel<<<(n + 255) / 256, 256>>>(out);
}